// round 12
// baseline (speedup 1.0000x reference)
#include <cuda_runtime.h>
#include <math.h>

// TSControllerCoordinateTransform: x [1,10,T] f32, reference_axis [3] f32
// -> out [2,3,T] f32 (rows 0..2 = basis @ (Xpos - refPos), rows 3..5 = x rows 7..9)

#define T_LEN 4000000
#define T4 (T_LEN / 4)
#define NB 592          // 4 blocks/SM x 148 SMs: all CTAs co-resident in wave 1
#define BLK 256

// Per-block partial sums: S0,S1,S2, S00,S01,S02,S11,S12,S22
__device__ double g_part[NB][9];
// Monotone barrier ticket counter (never reset -> safe across graph replays)
__device__ unsigned long long g_bar;

// ---------------------------------------------------------------------------
// Single persistent kernel: reduce+copy -> grid barrier -> redundant finalize
// -> transform. No inter-kernel launch gaps.
// ---------------------------------------------------------------------------
__global__ __launch_bounds__(BLK, 4) void k_all(const float4* __restrict__ x4,
                                                const float* __restrict__ x,
                                                const float* __restrict__ ref_axis,
                                                float4* __restrict__ out) {
    const int tid = threadIdx.x;

    // =============== Phase A: covariance reduce + Add-row copy ===============
    float s[9];
#pragma unroll
    for (int j = 0; j < 9; j++) s[j] = 0.0f;

    const int stride = NB * BLK;
    for (int i = blockIdx.x * BLK + tid; i < T4; i += stride) {
        // Batch all 6 global loads up front (MLP).
        const float4 a = x4[i];               // Xpos rows: default policy -> L2
        const float4 b = x4[T4 + i];
        const float4 c = x4[2 * T4 + i];
        const float4 d = __ldcs(&x4[7 * T4 + i]);   // Add rows: streamed
        const float4 e = __ldcs(&x4[8 * T4 + i]);
        const float4 f = __ldcs(&x4[9 * T4 + i]);

        __stcs(&out[3 * T4 + i], d);
        __stcs(&out[4 * T4 + i], e);
        __stcs(&out[5 * T4 + i], f);

        s[0] += (a.x + a.y) + (a.z + a.w);
        s[1] += (b.x + b.y) + (b.z + b.w);
        s[2] += (c.x + c.y) + (c.z + c.w);
        s[3] += (a.x * a.x + a.y * a.y) + (a.z * a.z + a.w * a.w);
        s[4] += (a.x * b.x + a.y * b.y) + (a.z * b.z + a.w * b.w);
        s[5] += (a.x * c.x + a.y * c.y) + (a.z * c.z + a.w * c.w);
        s[6] += (b.x * b.x + b.y * b.y) + (b.z * b.z + b.w * b.w);
        s[7] += (b.x * c.x + b.y * c.y) + (b.z * c.z + b.w * c.w);
        s[8] += (c.x * c.x + c.y * c.y) + (c.z * c.z + c.w * c.w);
    }

#pragma unroll
    for (int off = 16; off > 0; off >>= 1) {
#pragma unroll
        for (int j = 0; j < 9; j++)
            s[j] += __shfl_down_sync(0xFFFFFFFFu, s[j], off);
    }

    __shared__ float smf[8][9];
    {
        const int wid = tid >> 5, lid = tid & 31;
        if (lid == 0) {
#pragma unroll
            for (int j = 0; j < 9; j++) smf[wid][j] = s[j];
        }
    }
    __syncthreads();
    if (tid < 9) {
        double t = 0.0;
#pragma unroll
        for (int w = 0; w < 8; w++) t += (double)smf[w][tid];
        g_part[blockIdx.x][tid] = t;
    }

    // =============== Grid barrier (ticket/generation, replay-safe) ==========
    __shared__ unsigned long long s_target;
    __threadfence();          // make g_part visible before arrival
    __syncthreads();
    if (tid == 0) {
        const unsigned long long old = atomicAdd(&g_bar, 1ULL);
        const unsigned long long gen = old / (unsigned long long)NB;
        s_target = (gen + 1ULL) * (unsigned long long)NB;
    }
    __syncthreads();
    if (tid == 0) {
        volatile unsigned long long* p = &g_bar;
        while (*p < s_target) { }
    }
    __syncthreads();
    __threadfence();          // acquire side

    // =============== Phase B: redundant per-block finalize ==================
    __shared__ double ssum[9];
    __shared__ float s_params[12];
    {
        double t[9];
#pragma unroll
        for (int j = 0; j < 9; j++) t[j] = 0.0;
        for (int i = tid; i < NB; i += BLK) {
#pragma unroll
            for (int j = 0; j < 9; j++) t[j] += __ldcg(&g_part[i][j]);
        }
#pragma unroll
        for (int off = 16; off > 0; off >>= 1) {
#pragma unroll
            for (int j = 0; j < 9; j++)
                t[j] += __shfl_down_sync(0xFFFFFFFFu, t[j], off);
        }
        __shared__ double smd[8][9];
        const int wid = tid >> 5, lid = tid & 31;
        if (lid == 0) {
#pragma unroll
            for (int j = 0; j < 9; j++) smd[wid][j] = t[j];
        }
        __syncthreads();
        if (tid < 9) {
            double u = 0.0;
#pragma unroll
            for (int w = 0; w < 8; w++) u += smd[w][tid];
            ssum[tid] = u;
        }
        __syncthreads();
    }

    if (tid == 0) {
        const double T = (double)T_LEN;
        const double S0 = ssum[0], S1 = ssum[1], S2 = ssum[2];
        const double inv = 1.0 / (T - 1.0);
        const double a00 = (ssum[3] - S0 * S0 / T) * inv;
        const double a01 = (ssum[4] - S0 * S1 / T) * inv;
        const double a02 = (ssum[5] - S0 * S2 / T) * inv;
        const double a11 = (ssum[6] - S1 * S1 / T) * inv;
        const double a12 = (ssum[7] - S1 * S2 / T) * inv;
        const double a22 = (ssum[8] - S2 * S2 / T) * inv;

        // Closed-form largest eigenvalue (trigonometric method)
        const double m = (a00 + a11 + a22) * (1.0 / 3.0);
        const double d0 = a00 - m, d1 = a11 - m, d2 = a22 - m;
        const double p2 = d0 * d0 + d1 * d1 + d2 * d2 +
                          2.0 * (a01 * a01 + a02 * a02 + a12 * a12);
        double z0, z1, z2;
        if (p2 < 1e-300) {
            z0 = 0.0; z1 = 0.0; z2 = 1.0;
        } else {
            const double p = sqrt(p2 * (1.0 / 6.0));
            const double ip = 1.0 / p;
            const double b00 = d0 * ip, b11 = d1 * ip, b22 = d2 * ip;
            const double o01 = a01 * ip, o02 = a02 * ip, o12 = a12 * ip;
            double r = 0.5 * (b00 * (b11 * b22 - o12 * o12)
                            - o01 * (o01 * b22 - o12 * o02)
                            + o02 * (o01 * o12 - b11 * o02));
            r = fmin(1.0, fmax(-1.0, r));
            const double phi = acos(r) * (1.0 / 3.0);
            const double lam = m + 2.0 * p * cos(phi);   // largest eigenvalue

            // Eigenvector: best cross product of rows of (A - lam I)
            const double c00 = a00 - lam, c11 = a11 - lam, c22 = a22 - lam;
            double v0, v1, v2, best = -1.0;
            {   // row0 x row1
                const double e0 = a01 * a12 - a02 * c11;
                const double e1 = a02 * a01 - c00 * a12;
                const double e2 = c00 * c11 - a01 * a01;
                const double n = e0 * e0 + e1 * e1 + e2 * e2;
                v0 = e0; v1 = e1; v2 = e2; best = n;
            }
            {   // row0 x row2
                const double e0 = a01 * c22 - a02 * a12;
                const double e1 = a02 * a02 - c00 * c22;
                const double e2 = c00 * a12 - a01 * a02;
                const double n = e0 * e0 + e1 * e1 + e2 * e2;
                if (n > best) { v0 = e0; v1 = e1; v2 = e2; best = n; }
            }
            {   // row1 x row2
                const double e0 = c11 * c22 - a12 * a12;
                const double e1 = a12 * a02 - a01 * c22;
                const double e2 = a01 * a12 - c11 * a02;
                const double n = e0 * e0 + e1 * e1 + e2 * e2;
                if (n > best) { v0 = e0; v1 = e1; v2 = e2; best = n; }
            }
            const double rn = 1.0 / sqrt(best);
            z0 = v0 * rn; z1 = v1 * rn; z2 = v2 * rn;
        }

        // Quaternion forward axis (raw, unnormalized Qrot — matches reference)
        const double qx = (double)x[3 * T_LEN];
        const double qy = (double)x[4 * T_LEN];
        const double qz = (double)x[5 * T_LEN];
        const double qw = (double)x[6 * T_LEN];
        const double zf0 = 2.0 * (qx * qz + qw * qy);
        const double zf1 = 2.0 * (qy * qz - qw * qx);
        const double zf2 = 1.0 - 2.0 * (qx * qx + qy * qy);

        if (zf0 * z0 + zf1 * z1 + zf2 * z2 < 0.0) {
            z0 = -z0; z1 = -z1; z2 = -z2;
        }

        const double u0 = (double)ref_axis[0], u1 = (double)ref_axis[1],
                     u2 = (double)ref_axis[2];
        const double r0 = u1 * z2 - u2 * z1;   // new_right = cross(up, z)
        const double r1 = u2 * z0 - u0 * z2;
        const double r2 = u0 * z1 - u1 * z0;
        const double f0 = r1 * u2 - r2 * u1;   // new_fwd = cross(right, up)
        const double f1 = r2 * u0 - r0 * u2;
        const double f2 = r0 * u1 - r1 * u0;

        const double p0 = (double)x[0];        // refPos = Xpos[:, :, 0]
        const double p1 = (double)x[T_LEN];
        const double p2r = (double)x[2 * T_LEN];

        const double B[3][3] = {{r0, r1, r2}, {u0, u1, u2}, {f0, f1, f2}};
#pragma unroll
        for (int i = 0; i < 3; i++) {
            s_params[3 * i + 0] = (float)B[i][0];
            s_params[3 * i + 1] = (float)B[i][1];
            s_params[3 * i + 2] = (float)B[i][2];
            s_params[9 + i] = (float)(B[i][0] * p0 + B[i][1] * p1 + B[i][2] * p2r);
        }
    }
    __syncthreads();

    const float b00 = s_params[0], b01 = s_params[1], b02 = s_params[2];
    const float b10 = s_params[3], b11 = s_params[4], b12 = s_params[5];
    const float b20 = s_params[6], b21 = s_params[7], b22 = s_params[8];
    const float o0 = s_params[9], o1 = s_params[10], o2 = s_params[11];

    // =============== Phase C: Xpos transform (L2-hot reads) =================
    for (int i = blockIdx.x * BLK + tid; i < T4; i += stride) {
        const float4 a = x4[i];
        const float4 b = x4[T4 + i];
        const float4 c = x4[2 * T4 + i];

        float4 y0, y1, y2;
        y0.x = fmaf(b00, a.x, fmaf(b01, b.x, fmaf(b02, c.x, -o0)));
        y0.y = fmaf(b00, a.y, fmaf(b01, b.y, fmaf(b02, c.y, -o0)));
        y0.z = fmaf(b00, a.z, fmaf(b01, b.z, fmaf(b02, c.z, -o0)));
        y0.w = fmaf(b00, a.w, fmaf(b01, b.w, fmaf(b02, c.w, -o0)));

        y1.x = fmaf(b10, a.x, fmaf(b11, b.x, fmaf(b12, c.x, -o1)));
        y1.y = fmaf(b10, a.y, fmaf(b11, b.y, fmaf(b12, c.y, -o1)));
        y1.z = fmaf(b10, a.z, fmaf(b11, b.z, fmaf(b12, c.z, -o1)));
        y1.w = fmaf(b10, a.w, fmaf(b11, b.w, fmaf(b12, c.w, -o1)));

        y2.x = fmaf(b20, a.x, fmaf(b21, b.x, fmaf(b22, c.x, -o2)));
        y2.y = fmaf(b20, a.y, fmaf(b21, b.y, fmaf(b22, c.y, -o2)));
        y2.z = fmaf(b20, a.z, fmaf(b21, b.z, fmaf(b22, c.z, -o2)));
        y2.w = fmaf(b20, a.w, fmaf(b21, b.w, fmaf(b22, c.w, -o2)));

        __stcs(&out[i], y0);
        __stcs(&out[T4 + i], y1);
        __stcs(&out[2 * T4 + i], y2);
    }
}

// ---------------------------------------------------------------------------
extern "C" void kernel_launch(void* const* d_in, const int* in_sizes, int n_in,
                              void* d_out, int out_size) {
    const float* x = (const float*)d_in[0];
    const float* ref_axis = (const float*)d_in[1];
    float* out = (float*)d_out;

    k_all<<<NB, BLK>>>((const float4*)x, x, ref_axis, (float4*)out);
}

// round 13
// speedup vs baseline: 1.3061x; 1.3061x over previous
#include <cuda_runtime.h>
#include <math.h>

// TSControllerCoordinateTransform: x [1,10,T] f32, reference_axis [3] f32
// -> out [2,3,T] f32 (rows 0..2 = basis @ (Xpos - refPos), rows 3..5 = x rows 7..9)

#define T_LEN 4000000
#define T4 (T_LEN / 4)
#define NB_RED 1184   // 8 blocks/SM x 148 SMs

// Per-block partial sums: S0,S1,S2, S00,S01,S02,S11,S12,S22
__device__ double g_part[NB_RED][9];
// 12 transform params: basis row-major b[0..8], offsets o[0..2]
__device__ float g_params[12];
// Monotone arrival ticket (never reset -> replay-safe across graph replays)
__device__ unsigned long long g_tick;

// ---------------------------------------------------------------------------
// Kernel 1: FUSED covariance reduction (rows 0..2) + Add-row copy (rows 7..9)
// + last-block finalize (closed-form 3x3 eigh -> g_params).
// ---------------------------------------------------------------------------
__global__ __launch_bounds__(256) void k_reduce_copy(const float4* __restrict__ x4,
                                                     const float* __restrict__ x,
                                                     const float* __restrict__ ref_axis,
                                                     float4* __restrict__ out) {
    const int tid = threadIdx.x;

    float s[9];
#pragma unroll
    for (int j = 0; j < 9; j++) s[j] = 0.0f;

    const int stride = NB_RED * 256;
    for (int i = blockIdx.x * 256 + tid; i < T4; i += stride) {
        // Batch all 6 global loads up front (MLP).
        const float4 a = x4[i];               // Xpos rows: default policy -> stays in L2
        const float4 b = x4[T4 + i];
        const float4 c = x4[2 * T4 + i];
        const float4 d = __ldcs(&x4[7 * T4 + i]);   // Add rows: streamed
        const float4 e = __ldcs(&x4[8 * T4 + i]);
        const float4 f = __ldcs(&x4[9 * T4 + i]);

        // Copy-through of Add rows into out rows 3..5 (streamed stores).
        __stcs(&out[3 * T4 + i], d);
        __stcs(&out[4 * T4 + i], e);
        __stcs(&out[5 * T4 + i], f);

        s[0] += (a.x + a.y) + (a.z + a.w);
        s[1] += (b.x + b.y) + (b.z + b.w);
        s[2] += (c.x + c.y) + (c.z + c.w);
        s[3] += (a.x * a.x + a.y * a.y) + (a.z * a.z + a.w * a.w);
        s[4] += (a.x * b.x + a.y * b.y) + (a.z * b.z + a.w * b.w);
        s[5] += (a.x * c.x + a.y * c.y) + (a.z * c.z + a.w * c.w);
        s[6] += (b.x * b.x + b.y * b.y) + (b.z * b.z + b.w * b.w);
        s[7] += (b.x * c.x + b.y * c.y) + (b.z * c.z + b.w * c.w);
        s[8] += (c.x * c.x + c.y * c.y) + (c.z * c.z + c.w * c.w);
    }

#pragma unroll
    for (int off = 16; off > 0; off >>= 1) {
#pragma unroll
        for (int j = 0; j < 9; j++)
            s[j] += __shfl_down_sync(0xFFFFFFFFu, s[j], off);
    }

    __shared__ float smf[8][9];
    {
        const int wid = tid >> 5, lid = tid & 31;
        if (lid == 0) {
#pragma unroll
            for (int j = 0; j < 9; j++) smf[wid][j] = s[j];
        }
    }
    __syncthreads();
    if (tid < 9) {
        double t = 0.0;
#pragma unroll
        for (int w = 0; w < 8; w++) t += (double)smf[w][tid];
        g_part[blockIdx.x][tid] = t;
    }

    // ---- Last-block detection (monotone ticket, replay-safe) ----
    __shared__ int s_last;
    __threadfence();            // publish g_part before arrival
    __syncthreads();
    if (tid == 0) {
        const unsigned long long old = atomicAdd(&g_tick, 1ULL);
        s_last = ((old % (unsigned long long)NB_RED) ==
                  (unsigned long long)(NB_RED - 1)) ? 1 : 0;
    }
    __syncthreads();
    if (!s_last) return;

    // ---- Finalize (runs in the single last block) ----
    __shared__ double ssum[9];
    {
        double t[9];
#pragma unroll
        for (int j = 0; j < 9; j++) t[j] = 0.0;
        for (int i = tid; i < NB_RED; i += 256) {
#pragma unroll
            for (int j = 0; j < 9; j++) t[j] += __ldcg(&g_part[i][j]);
        }
#pragma unroll
        for (int off = 16; off > 0; off >>= 1) {
#pragma unroll
            for (int j = 0; j < 9; j++)
                t[j] += __shfl_down_sync(0xFFFFFFFFu, t[j], off);
        }
        __shared__ double smd[8][9];
        const int wid = tid >> 5, lid = tid & 31;
        if (lid == 0) {
#pragma unroll
            for (int j = 0; j < 9; j++) smd[wid][j] = t[j];
        }
        __syncthreads();
        if (tid < 9) {
            double u = 0.0;
#pragma unroll
            for (int w = 0; w < 8; w++) u += smd[w][tid];
            ssum[tid] = u;
        }
        __syncthreads();
    }
    if (tid != 0) return;

    const double T = (double)T_LEN;
    const double S0 = ssum[0], S1 = ssum[1], S2 = ssum[2];
    const double inv = 1.0 / (T - 1.0);
    const double a00 = (ssum[3] - S0 * S0 / T) * inv;
    const double a01 = (ssum[4] - S0 * S1 / T) * inv;
    const double a02 = (ssum[5] - S0 * S2 / T) * inv;
    const double a11 = (ssum[6] - S1 * S1 / T) * inv;
    const double a12 = (ssum[7] - S1 * S2 / T) * inv;
    const double a22 = (ssum[8] - S2 * S2 / T) * inv;

    // Closed-form largest eigenvalue (trigonometric method)
    const double m = (a00 + a11 + a22) * (1.0 / 3.0);
    const double d0 = a00 - m, d1 = a11 - m, d2 = a22 - m;
    const double p2 = d0 * d0 + d1 * d1 + d2 * d2 +
                      2.0 * (a01 * a01 + a02 * a02 + a12 * a12);
    double z0, z1, z2;
    if (p2 < 1e-300) {
        z0 = 0.0; z1 = 0.0; z2 = 1.0;
    } else {
        const double p = sqrt(p2 * (1.0 / 6.0));
        const double ip = 1.0 / p;
        const double b00 = d0 * ip, b11 = d1 * ip, b22 = d2 * ip;
        const double o01 = a01 * ip, o02 = a02 * ip, o12 = a12 * ip;
        double r = 0.5 * (b00 * (b11 * b22 - o12 * o12)
                        - o01 * (o01 * b22 - o12 * o02)
                        + o02 * (o01 * o12 - b11 * o02));
        r = fmin(1.0, fmax(-1.0, r));
        const double phi = acos(r) * (1.0 / 3.0);
        const double lam = m + 2.0 * p * cos(phi);   // largest eigenvalue

        // Eigenvector: best cross product of rows of (A - lam I)
        const double c00 = a00 - lam, c11 = a11 - lam, c22 = a22 - lam;
        double v0, v1, v2, best = -1.0;
        {   // row0 x row1
            const double e0 = a01 * a12 - a02 * c11;
            const double e1 = a02 * a01 - c00 * a12;
            const double e2 = c00 * c11 - a01 * a01;
            const double n = e0 * e0 + e1 * e1 + e2 * e2;
            v0 = e0; v1 = e1; v2 = e2; best = n;
        }
        {   // row0 x row2
            const double e0 = a01 * c22 - a02 * a12;
            const double e1 = a02 * a02 - c00 * c22;
            const double e2 = c00 * a12 - a01 * a02;
            const double n = e0 * e0 + e1 * e1 + e2 * e2;
            if (n > best) { v0 = e0; v1 = e1; v2 = e2; best = n; }
        }
        {   // row1 x row2
            const double e0 = c11 * c22 - a12 * a12;
            const double e1 = a12 * a02 - a01 * c22;
            const double e2 = a01 * a12 - c11 * a02;
            const double n = e0 * e0 + e1 * e1 + e2 * e2;
            if (n > best) { v0 = e0; v1 = e1; v2 = e2; best = n; }
        }
        const double rn = 1.0 / sqrt(best);
        z0 = v0 * rn; z1 = v1 * rn; z2 = v2 * rn;
    }

    // Quaternion forward axis (raw, unnormalized Qrot — matches reference)
    const double qx = (double)x[3 * T_LEN];
    const double qy = (double)x[4 * T_LEN];
    const double qz = (double)x[5 * T_LEN];
    const double qw = (double)x[6 * T_LEN];
    const double zf0 = 2.0 * (qx * qz + qw * qy);
    const double zf1 = 2.0 * (qy * qz - qw * qx);
    const double zf2 = 1.0 - 2.0 * (qx * qx + qy * qy);

    if (zf0 * z0 + zf1 * z1 + zf2 * z2 < 0.0) {
        z0 = -z0; z1 = -z1; z2 = -z2;
    }

    const double u0 = (double)ref_axis[0], u1 = (double)ref_axis[1],
                 u2 = (double)ref_axis[2];
    const double r0 = u1 * z2 - u2 * z1;   // new_right = cross(up, z)
    const double r1 = u2 * z0 - u0 * z2;
    const double r2 = u0 * z1 - u1 * z0;
    const double f0 = r1 * u2 - r2 * u1;   // new_fwd = cross(right, up)
    const double f1 = r2 * u0 - r0 * u2;
    const double f2 = r0 * u1 - r1 * u0;

    const double p0 = (double)x[0];        // refPos = Xpos[:, :, 0]
    const double p1 = (double)x[T_LEN];
    const double p2r = (double)x[2 * T_LEN];

    const double B[3][3] = {{r0, r1, r2}, {u0, u1, u2}, {f0, f1, f2}};
#pragma unroll
    for (int i = 0; i < 3; i++) {
        g_params[3 * i + 0] = (float)B[i][0];
        g_params[3 * i + 1] = (float)B[i][1];
        g_params[3 * i + 2] = (float)B[i][2];
        g_params[9 + i] = (float)(B[i][0] * p0 + B[i][1] * p1 + B[i][2] * p2r);
    }
    // Kernel boundary publishes g_params to k_transform.
}

// ---------------------------------------------------------------------------
// Kernel 2: Xpos transform only. Reads largely L2-hot (warmed by kernel 1);
// output streamed.
// ---------------------------------------------------------------------------
__global__ __launch_bounds__(256) void k_transform(const float4* __restrict__ x,
                                                   float4* __restrict__ out) {
    const int i = blockIdx.x * blockDim.x + threadIdx.x;
    if (i >= T4) return;

    const float4 a = x[i];
    const float4 b = x[T4 + i];
    const float4 c = x[2 * T4 + i];

    const float b00 = g_params[0], b01 = g_params[1], b02 = g_params[2];
    const float b10 = g_params[3], b11 = g_params[4], b12 = g_params[5];
    const float b20 = g_params[6], b21 = g_params[7], b22 = g_params[8];
    const float o0 = g_params[9], o1 = g_params[10], o2 = g_params[11];

    float4 y0, y1, y2;
    y0.x = fmaf(b00, a.x, fmaf(b01, b.x, fmaf(b02, c.x, -o0)));
    y0.y = fmaf(b00, a.y, fmaf(b01, b.y, fmaf(b02, c.y, -o0)));
    y0.z = fmaf(b00, a.z, fmaf(b01, b.z, fmaf(b02, c.z, -o0)));
    y0.w = fmaf(b00, a.w, fmaf(b01, b.w, fmaf(b02, c.w, -o0)));

    y1.x = fmaf(b10, a.x, fmaf(b11, b.x, fmaf(b12, c.x, -o1)));
    y1.y = fmaf(b10, a.y, fmaf(b11, b.y, fmaf(b12, c.y, -o1)));
    y1.z = fmaf(b10, a.z, fmaf(b11, b.z, fmaf(b12, c.z, -o1)));
    y1.w = fmaf(b10, a.w, fmaf(b11, b.w, fmaf(b12, c.w, -o1)));

    y2.x = fmaf(b20, a.x, fmaf(b21, b.x, fmaf(b22, c.x, -o2)));
    y2.y = fmaf(b20, a.y, fmaf(b21, b.y, fmaf(b22, c.y, -o2)));
    y2.z = fmaf(b20, a.z, fmaf(b21, b.z, fmaf(b22, c.z, -o2)));
    y2.w = fmaf(b20, a.w, fmaf(b21, b.w, fmaf(b22, c.w, -o2)));

    __stcs(&out[i], y0);
    __stcs(&out[T4 + i], y1);
    __stcs(&out[2 * T4 + i], y2);
}

// ---------------------------------------------------------------------------
extern "C" void kernel_launch(void* const* d_in, const int* in_sizes, int n_in,
                              void* d_out, int out_size) {
    const float* x = (const float*)d_in[0];
    const float* ref_axis = (const float*)d_in[1];
    float* out = (float*)d_out;

    k_reduce_copy<<<NB_RED, 256>>>((const float4*)x, x, ref_axis, (float4*)out);
    k_transform<<<(T4 + 255) / 256, 256>>>((const float4*)x, (float4*)out);
}

// round 15
// speedup vs baseline: 1.3689x; 1.0481x over previous
#include <cuda_runtime.h>
#include <math.h>

// TSControllerCoordinateTransform: x [1,10,T] f32, reference_axis [3] f32
// -> out [2,3,T] f32 (rows 0..2 = basis @ (Xpos - refPos), rows 3..5 = x rows 7..9)

#define T_LEN 4000000
#define T4 (T_LEN / 4)
#define T4H (T4 / 2)
#define NB_RED 1184   // reduce grid size (must match launch)

// Per-block partial sums: S0,S1,S2, S00,S01,S02,S11,S12,S22
__device__ double g_part[NB_RED][9];
// 12 transform params: basis row-major b[0..8], offsets o[0..2]
__device__ float g_params[12];

// ---------------------------------------------------------------------------
// Kernel 1: FUSED covariance reduction (rows 0..2) + Add-row copy (rows 7..9).
// 6 independent loads in flight per iteration; copy streamed to keep Xpos in L2.
// ---------------------------------------------------------------------------
__global__ __launch_bounds__(256) void k_reduce_copy(const float4* __restrict__ x,
                                                     float4* __restrict__ out) {
    float s[9];
#pragma unroll
    for (int j = 0; j < 9; j++) s[j] = 0.0f;

    const int stride = NB_RED * 256;
    for (int i = blockIdx.x * 256 + threadIdx.x; i < T4; i += stride) {
        const float4 a = x[i];               // Xpos rows: default policy -> L2
        const float4 b = x[T4 + i];
        const float4 c = x[2 * T4 + i];
        const float4 d = __ldcs(&x[7 * T4 + i]);   // Add rows: streamed
        const float4 e = __ldcs(&x[8 * T4 + i]);
        const float4 f = __ldcs(&x[9 * T4 + i]);

        __stcs(&out[3 * T4 + i], d);
        __stcs(&out[4 * T4 + i], e);
        __stcs(&out[5 * T4 + i], f);

        s[0] += (a.x + a.y) + (a.z + a.w);
        s[1] += (b.x + b.y) + (b.z + b.w);
        s[2] += (c.x + c.y) + (c.z + c.w);
        s[3] += (a.x * a.x + a.y * a.y) + (a.z * a.z + a.w * a.w);
        s[4] += (a.x * b.x + a.y * b.y) + (a.z * b.z + a.w * b.w);
        s[5] += (a.x * c.x + a.y * c.y) + (a.z * c.z + a.w * c.w);
        s[6] += (b.x * b.x + b.y * b.y) + (b.z * b.z + b.w * b.w);
        s[7] += (b.x * c.x + b.y * c.y) + (b.z * c.z + b.w * c.w);
        s[8] += (c.x * c.x + c.y * c.y) + (c.z * c.z + c.w * c.w);
    }

#pragma unroll
    for (int off = 16; off > 0; off >>= 1) {
#pragma unroll
        for (int j = 0; j < 9; j++)
            s[j] += __shfl_down_sync(0xFFFFFFFFu, s[j], off);
    }

    __shared__ float sm[8][9];
    const int wid = threadIdx.x >> 5;
    const int lid = threadIdx.x & 31;
    if (lid == 0) {
#pragma unroll
        for (int j = 0; j < 9; j++) sm[wid][j] = s[j];
    }
    __syncthreads();

    if (threadIdx.x < 9) {
        double t = 0.0;
#pragma unroll
        for (int w = 0; w < 8; w++) t += (double)sm[w][threadIdx.x];
        g_part[blockIdx.x][threadIdx.x] = t;
    }
}

// ---------------------------------------------------------------------------
// Kernel 2: finalize — sum partials (9 warps), closed-form 3x3 eigh (fp64),
// quaternion sign fix, cross-product basis, store 12 float params.
// ---------------------------------------------------------------------------
__global__ void k_finalize(const float* __restrict__ x,
                           const float* __restrict__ ref_axis) {
    __shared__ double ssum[9];
    const int w = threadIdx.x >> 5;   // component index 0..8
    const int lane = threadIdx.x & 31;

    if (w < 9) {
        double t = 0.0;
        for (int i = lane; i < NB_RED; i += 32) t += g_part[i][w];
#pragma unroll
        for (int off = 16; off > 0; off >>= 1)
            t += __shfl_down_sync(0xFFFFFFFFu, t, off);
        if (lane == 0) ssum[w] = t;
    }
    __syncthreads();
    if (threadIdx.x != 0) return;

    const double T = (double)T_LEN;
    const double S0 = ssum[0], S1 = ssum[1], S2 = ssum[2];
    const double inv = 1.0 / (T - 1.0);
    const double a00 = (ssum[3] - S0 * S0 / T) * inv;
    const double a01 = (ssum[4] - S0 * S1 / T) * inv;
    const double a02 = (ssum[5] - S0 * S2 / T) * inv;
    const double a11 = (ssum[6] - S1 * S1 / T) * inv;
    const double a12 = (ssum[7] - S1 * S2 / T) * inv;
    const double a22 = (ssum[8] - S2 * S2 / T) * inv;

    // Closed-form largest eigenvalue (trigonometric method)
    const double m = (a00 + a11 + a22) * (1.0 / 3.0);
    const double d0 = a00 - m, d1 = a11 - m, d2 = a22 - m;
    const double p2 = d0 * d0 + d1 * d1 + d2 * d2 +
                      2.0 * (a01 * a01 + a02 * a02 + a12 * a12);
    double z0, z1, z2;
    if (p2 < 1e-300) {
        z0 = 0.0; z1 = 0.0; z2 = 1.0;
    } else {
        const double p = sqrt(p2 * (1.0 / 6.0));
        const double ip = 1.0 / p;
        const double b00 = d0 * ip, b11 = d1 * ip, b22 = d2 * ip;
        const double o01 = a01 * ip, o02 = a02 * ip, o12 = a12 * ip;
        double r = 0.5 * (b00 * (b11 * b22 - o12 * o12)
                        - o01 * (o01 * b22 - o12 * o02)
                        + o02 * (o01 * o12 - b11 * o02));
        r = fmin(1.0, fmax(-1.0, r));
        const double phi = acos(r) * (1.0 / 3.0);
        const double lam = m + 2.0 * p * cos(phi);   // largest eigenvalue

        // Eigenvector: best cross product of rows of (A - lam I)
        const double c00 = a00 - lam, c11 = a11 - lam, c22 = a22 - lam;
        double v0, v1, v2, best = -1.0;
        {   // row0 x row1
            const double e0 = a01 * a12 - a02 * c11;
            const double e1 = a02 * a01 - c00 * a12;
            const double e2 = c00 * c11 - a01 * a01;
            const double n = e0 * e0 + e1 * e1 + e2 * e2;
            v0 = e0; v1 = e1; v2 = e2; best = n;
        }
        {   // row0 x row2
            const double e0 = a01 * c22 - a02 * a12;
            const double e1 = a02 * a02 - c00 * c22;
            const double e2 = c00 * a12 - a01 * a02;
            const double n = e0 * e0 + e1 * e1 + e2 * e2;
            if (n > best) { v0 = e0; v1 = e1; v2 = e2; best = n; }
        }
        {   // row1 x row2
            const double e0 = c11 * c22 - a12 * a12;
            const double e1 = a12 * a02 - a01 * c22;
            const double e2 = a01 * a12 - c11 * a02;
            const double n = e0 * e0 + e1 * e1 + e2 * e2;
            if (n > best) { v0 = e0; v1 = e1; v2 = e2; best = n; }
        }
        const double rn = 1.0 / sqrt(best);
        z0 = v0 * rn; z1 = v1 * rn; z2 = v2 * rn;
    }

    // Quaternion forward axis (raw, unnormalized Qrot — matches reference)
    const double qx = (double)x[3 * T_LEN];
    const double qy = (double)x[4 * T_LEN];
    const double qz = (double)x[5 * T_LEN];
    const double qw = (double)x[6 * T_LEN];
    const double zf0 = 2.0 * (qx * qz + qw * qy);
    const double zf1 = 2.0 * (qy * qz - qw * qx);
    const double zf2 = 1.0 - 2.0 * (qx * qx + qy * qy);

    if (zf0 * z0 + zf1 * z1 + zf2 * z2 < 0.0) {
        z0 = -z0; z1 = -z1; z2 = -z2;
    }

    const double u0 = (double)ref_axis[0], u1 = (double)ref_axis[1],
                 u2 = (double)ref_axis[2];
    const double r0 = u1 * z2 - u2 * z1;   // new_right = cross(up, z)
    const double r1 = u2 * z0 - u0 * z2;
    const double r2 = u0 * z1 - u1 * z0;
    const double f0 = r1 * u2 - r2 * u1;   // new_fwd = cross(right, up)
    const double f1 = r2 * u0 - r0 * u2;
    const double f2 = r0 * u1 - r1 * u0;

    const double p0 = (double)x[0];        // refPos = Xpos[:, :, 0]
    const double p1 = (double)x[T_LEN];
    const double p2r = (double)x[2 * T_LEN];

    const double B[3][3] = {{r0, r1, r2}, {u0, u1, u2}, {f0, f1, f2}};
#pragma unroll
    for (int i = 0; i < 3; i++) {
        g_params[3 * i + 0] = (float)B[i][0];
        g_params[3 * i + 1] = (float)B[i][1];
        g_params[3 * i + 2] = (float)B[i][2];
        g_params[9 + i] = (float)(B[i][0] * p0 + B[i][1] * p1 + B[i][2] * p2r);
    }
}

// ---------------------------------------------------------------------------
// Kernel 3: Xpos transform, 2 tiles per thread (6 loads in flight for MLP).
// Thread handles tile i and tile i + T4/2. Reads largely L2-hot; writes streamed.
// ---------------------------------------------------------------------------
__global__ __launch_bounds__(256) void k_transform(const float4* __restrict__ x,
                                                   float4* __restrict__ out) {
    const int i = blockIdx.x * blockDim.x + threadIdx.x;
    if (i >= T4H) return;
    const int j = i + T4H;

    // Batch all 6 global loads up front.
    const float4 a0 = x[i];
    const float4 b0 = x[T4 + i];
    const float4 c0 = x[2 * T4 + i];
    const float4 a1 = x[j];
    const float4 b1 = x[T4 + j];
    const float4 c1 = x[2 * T4 + j];

    const float b00 = g_params[0], b01 = g_params[1], b02 = g_params[2];
    const float b10 = g_params[3], b11 = g_params[4], b12 = g_params[5];
    const float b20 = g_params[6], b21 = g_params[7], b22 = g_params[8];
    const float o0 = g_params[9], o1 = g_params[10], o2 = g_params[11];

    float4 y0, y1, y2, w0, w1, w2;

    y0.x = fmaf(b00, a0.x, fmaf(b01, b0.x, fmaf(b02, c0.x, -o0)));
    y0.y = fmaf(b00, a0.y, fmaf(b01, b0.y, fmaf(b02, c0.y, -o0)));
    y0.z = fmaf(b00, a0.z, fmaf(b01, b0.z, fmaf(b02, c0.z, -o0)));
    y0.w = fmaf(b00, a0.w, fmaf(b01, b0.w, fmaf(b02, c0.w, -o0)));

    y1.x = fmaf(b10, a0.x, fmaf(b11, b0.x, fmaf(b12, c0.x, -o1)));
    y1.y = fmaf(b10, a0.y, fmaf(b11, b0.y, fmaf(b12, c0.y, -o1)));
    y1.z = fmaf(b10, a0.z, fmaf(b11, b0.z, fmaf(b12, c0.z, -o1)));
    y1.w = fmaf(b10, a0.w, fmaf(b11, b0.w, fmaf(b12, c0.w, -o1)));

    y2.x = fmaf(b20, a0.x, fmaf(b21, b0.x, fmaf(b22, c0.x, -o2)));
    y2.y = fmaf(b20, a0.y, fmaf(b21, b0.y, fmaf(b22, c0.y, -o2)));
    y2.z = fmaf(b20, a0.z, fmaf(b21, b0.z, fmaf(b22, c0.z, -o2)));
    y2.w = fmaf(b20, a0.w, fmaf(b21, b0.w, fmaf(b22, c0.w, -o2)));

    w0.x = fmaf(b00, a1.x, fmaf(b01, b1.x, fmaf(b02, c1.x, -o0)));
    w0.y = fmaf(b00, a1.y, fmaf(b01, b1.y, fmaf(b02, c1.y, -o0)));
    w0.z = fmaf(b00, a1.z, fmaf(b01, b1.z, fmaf(b02, c1.z, -o0)));
    w0.w = fmaf(b00, a1.w, fmaf(b01, b1.w, fmaf(b02, c1.w, -o0)));

    w1.x = fmaf(b10, a1.x, fmaf(b11, b1.x, fmaf(b12, c1.x, -o1)));
    w1.y = fmaf(b10, a1.y, fmaf(b11, b1.y, fmaf(b12, c1.y, -o1)));
    w1.z = fmaf(b10, a1.z, fmaf(b11, b1.z, fmaf(b12, c1.z, -o1)));
    w1.w = fmaf(b10, a1.w, fmaf(b11, b1.w, fmaf(b12, c1.w, -o1)));

    w2.x = fmaf(b20, a1.x, fmaf(b21, b1.x, fmaf(b22, c1.x, -o2)));
    w2.y = fmaf(b20, a1.y, fmaf(b21, b1.y, fmaf(b22, c1.y, -o2)));
    w2.z = fmaf(b20, a1.z, fmaf(b21, b1.z, fmaf(b22, c1.z, -o2)));
    w2.w = fmaf(b20, a1.w, fmaf(b21, b1.w, fmaf(b22, c1.w, -o2)));

    __stcs(&out[i], y0);
    __stcs(&out[T4 + i], y1);
    __stcs(&out[2 * T4 + i], y2);
    __stcs(&out[j], w0);
    __stcs(&out[T4 + j], w1);
    __stcs(&out[2 * T4 + j], w2);
}

// ---------------------------------------------------------------------------
extern "C" void kernel_launch(void* const* d_in, const int* in_sizes, int n_in,
                              void* d_out, int out_size) {
    const float* x = (const float*)d_in[0];
    const float* ref_axis = (const float*)d_in[1];
    float* out = (float*)d_out;

    k_reduce_copy<<<NB_RED, 256>>>((const float4*)x, (float4*)out);
    k_finalize<<<1, 288>>>(x, ref_axis);
    k_transform<<<(T4H + 255) / 256, 256>>>((const float4*)x, (float4*)out);
}